// round 16
// baseline (speedup 1.0000x reference)
#include <cuda_runtime.h>
#include <cuda_fp16.h>
#include <math.h>
#include <stdint.h>

#define B_ 8
#define N_ 512
#define D_ 512
#define H_ 8
#define DK_ 64
#define BNT 4096                 // B*N
#define NN_ 262144               // N*N

// ---------------- scratch (static device globals; no allocation allowed) ----
__device__ float g_q [BNT * D_];
__device__ float g_k [BNT * D_];
__device__ float g_v [BNT * D_];
__device__ float g_ao[BNT * D_];
__device__ __half g_F [(long long)B_ * H_ * NN_];  // geometry factor * mask, fp16
__device__ float g_cx[BNT], g_cy[BNT], g_iw[BNT], g_ih[BNT], g_no[BNT];
__device__ float g_tw[32][BNT];   // per-box sin/cos tables

// 100 / 1000^(m/8)
__constant__ float c_DM[8] = {
    100.0f, 42.169650342858224f, 17.78279410038923f, 7.498942093324559f,
    3.1622776601683795f, 1.3335214321633242f, 0.5623413251903491f, 0.23713737056616555f};

// Cody-Waite reduced fast sincos
__device__ __forceinline__ void fsincos(float x, float& s, float& c) {
    float k = rintf(x * 0.15915494309189535f);
    float r = __fmaf_rn(k, -6.28125f, x);
    r = __fmaf_rn(k, -1.9353071795864769e-3f, r);
    s = __sinf(r);
    c = __cosf(r);
}

__device__ __forceinline__ float fex2(float x) {
    float r;
    asm("ex2.approx.f32 %0, %1;" : "=f"(r) : "f"(x));
    return r;
}

// ---------------- per-box precompute (detect folded in) ---------------------
__global__ void box_pre(const float* __restrict__ box, const void* __restrict__ nobj) {
    int t = threadIdx.x;
    int i = blockIdx.x * blockDim.x + t;
    int v = 0;
    for (int k = t; k < 1024; k += blockDim.x) {
        int x = ((const int*)nobj)[k];
        v |= (x != 0 && x != 1);
    }
    int isbyte = __syncthreads_or(v);
    if (i >= BNT) return;
    float x0 = box[4*i+0], y0 = box[4*i+1], x1 = box[4*i+2], y1 = box[4*i+3];
    float w = x1 - x0 + 1.0f, h = y1 - y0 + 1.0f;
    g_cx[i] = 0.5f * (x0 + x1);
    g_cy[i] = 0.5f * (y0 + y1);
    g_iw[i] = 1.0f / w;
    g_ih[i] = 1.0f / h;
    float lw = logf(w), lh = logf(h);
    #pragma unroll
    for (int m = 0; m < 8; m++) {
        float s, c;
        fsincos(c_DM[m] * lw, s, c);
        g_tw[m][i] = s;      g_tw[8 + m][i] = c;
        fsincos(c_DM[m] * lh, s, c);
        g_tw[16 + m][i] = s; g_tw[24 + m][i] = c;
    }
    int nv = isbyte ? (int)((const unsigned char*)nobj)[i]
                    : ((const int*)nobj)[i];
    g_no[i] = nv ? 1.0f : 0.0f;
}

// ---------------- BF16 2-plane helpers --------------------------------------
__device__ __forceinline__ uint32_t pack_bf(float e, float o) {
    uint32_t r;
    asm("cvt.rn.bf16x2.f32 %0, %1, %2;" : "=r"(r) : "f"(o), "f"(e));
    return r;
}
__device__ __forceinline__ uint32_t resid_bf(float e, float o, uint32_t hw) {
    float eh = __uint_as_float(hw << 16);
    float oh = __uint_as_float(hw & 0xffff0000u);
    return pack_bf(e - eh, o - oh);
}
__device__ __forceinline__ void mma_bf16(float* d, const uint32_t* a, const uint32_t* b) {
    asm("mma.sync.aligned.m16n8k16.row.col.f32.bf16.bf16.f32 "
        "{%0,%1,%2,%3}, {%4,%5,%6,%7}, {%8,%9}, {%0,%1,%2,%3};"
        : "+f"(d[0]), "+f"(d[1]), "+f"(d[2]), "+f"(d[3])
        : "r"(a[0]), "r"(a[1]), "r"(a[2]), "r"(a[3]), "r"(b[0]), "r"(b[1]));
}

// ================== geometry body (one (b,i) row, 128 threads) =============
#define GES 132
#define GEOM_WORDS (2 * 32 * GES)
__device__ __forceinline__ void geom_body(
    const float* __restrict__ WG, const float* __restrict__ bG,
    const int* __restrict__ msk, int row, int t, uint32_t* EP)
{
    int lane = t & 31, w = t >> 5;
    int frow = lane >> 2, fcol = lane & 3;
    int b = row >> 9, i = row & 511;
    int base = b << 9;
    int gi = base + i;
    float cxi = g_cx[gi], cyi = g_cy[gi], iwi = g_iw[gi], ihi = g_ih[gi];
    float noi = g_no[gi];
    const int* mrow = msk + b * N_;
    float swiW[8], cwiW[8], swiH[8], cwiH[8];
    #pragma unroll
    for (int m = 0; m < 8; m++) {
        swiW[m] = g_tw[m][gi];      cwiW[m] = g_tw[8 + m][gi];
        swiH[m] = g_tw[16 + m][gi]; cwiH[m] = g_tw[24 + m][gi];
    }
    uint32_t wbh[4][2], wbl[4][2];
    #pragma unroll
    for (int ks = 0; ks < 4; ks++) {
        float b00 = WG[frow * 64 + ks * 16 + 2 * fcol];
        float b01 = WG[frow * 64 + ks * 16 + 2 * fcol + 1];
        float b10 = WG[frow * 64 + ks * 16 + 2 * fcol + 8];
        float b11 = WG[frow * 64 + ks * 16 + 2 * fcol + 9];
        wbh[ks][0] = pack_bf(b00, b01); wbl[ks][0] = resid_bf(b00, b01, wbh[ks][0]);
        wbh[ks][1] = pack_bf(b10, b11); wbl[ks][1] = resid_bf(b10, b11, wbh[ks][1]);
    }
    float bg0 = bG[2 * fcol], bg1 = bG[2 * fcol + 1];
    long long obase = (long long)b * H_ * NN_ + (long long)i * N_;

    auto est = [&](int kw, float a, float bvv) {
        uint32_t hh = pack_bf(a, bvv);
        *(uint2*)&EP[2 * (kw * GES + t)] = make_uint2(hh, resid_bf(a, bvv, hh));
    };

    for (int jt = 0; jt < 4; jt++) {
        int j0 = jt << 7;
        int jj = base + j0 + t;
        __syncthreads();
        float dx = __logf(fmaxf(fabsf(g_cx[jj] - cxi) * iwi, 1e-3f));
        float dy = __logf(fmaxf(fabsf(g_cy[jj] - cyi) * ihi, 1e-3f));
        #pragma unroll
        for (int mp = 0; mp < 4; mp++) {
            int m0 = 2 * mp, m1 = m0 + 1;
            float s0, c0, s1, c1;
            fsincos(dx * c_DM[m0], s0, c0);
            fsincos(dx * c_DM[m1], s1, c1);
            est(mp, s0, s1); est(16 + mp, c0, c1);
            fsincos(dy * c_DM[m0], s0, c0);
            fsincos(dy * c_DM[m1], s1, c1);
            est(4 + mp, s0, s1); est(20 + mp, c0, c1);
            float swj0 = g_tw[m0][jj], cwj0 = g_tw[8 + m0][jj];
            float swj1 = g_tw[m1][jj], cwj1 = g_tw[8 + m1][jj];
            est(8 + mp,  swiW[m0]*cwj0 - cwiW[m0]*swj0, swiW[m1]*cwj1 - cwiW[m1]*swj1);
            est(24 + mp, cwiW[m0]*cwj0 + swiW[m0]*swj0, cwiW[m1]*cwj1 + swiW[m1]*swj1);
            float shj0 = g_tw[16 + m0][jj], chj0 = g_tw[24 + m0][jj];
            float shj1 = g_tw[16 + m1][jj], chj1 = g_tw[24 + m1][jj];
            est(12 + mp, swiH[m0]*chj0 - cwiH[m0]*shj0, swiH[m1]*chj1 - cwiH[m1]*shj1);
            est(28 + mp, cwiH[m0]*chj0 + swiH[m0]*shj0, cwiH[m1]*chj1 + swiH[m1]*shj1);
        }
        __syncthreads();
        float acc[2][4];
        #pragma unroll
        for (int mt = 0; mt < 2; mt++)
            #pragma unroll
            for (int r = 0; r < 4; r++) acc[mt][r] = 0.0f;
        #pragma unroll
        for (int ks = 0; ks < 4; ks++) {
            #pragma unroll
            for (int mt = 0; mt < 2; mt++) {
                int p = (w << 5) + (mt << 4) + frow;
                uint2 u0 = *(const uint2*)&EP[2 * ((ks*8 + fcol) * GES + p)];
                uint2 u1 = *(const uint2*)&EP[2 * ((ks*8 + fcol) * GES + p + 8)];
                uint2 u2 = *(const uint2*)&EP[2 * ((ks*8 + fcol + 4) * GES + p)];
                uint2 u3 = *(const uint2*)&EP[2 * ((ks*8 + fcol + 4) * GES + p + 8)];
                uint32_t ah[4] = {u0.x, u1.x, u2.x, u3.x};
                uint32_t al[4] = {u0.y, u1.y, u2.y, u3.y};
                mma_bf16(acc[mt], ah, wbh[ks]);
                mma_bf16(acc[mt], ah, wbl[ks]);
                mma_bf16(acc[mt], al, wbh[ks]);
            }
        }
        #pragma unroll
        for (int mt = 0; mt < 2; mt++) {
            int r0 = (w << 5) + (mt << 4) + frow;
            int r1 = r0 + 8;
            bool obj0 = (fmaxf(noi, g_no[base + j0 + r0]) < 0.5f);
            bool obj1 = (fmaxf(noi, g_no[base + j0 + r1]) < 0.5f);
            float mk0 = mrow[j0 + r0] ? 1.0f : 0.0f;
            float mk1 = mrow[j0 + r1] ? 1.0f : 0.0f;
            float v00 = acc[mt][0] + bg0, v01 = acc[mt][1] + bg1;
            float v10 = acc[mt][2] + bg0, v11 = acc[mt][3] + bg1;
            long long h0 = (long long)(2 * fcol) * NN_;
            long long h1 = h0 + NN_;
            g_F[obase + h0 + j0 + r0] = __float2half((obj0 ? fmaxf(v00, 1e-6f) : 1.0f) * mk0);
            g_F[obase + h1 + j0 + r0] = __float2half((obj0 ? fmaxf(v01, 1e-6f) : 1.0f) * mk0);
            g_F[obase + h0 + j0 + r1] = __float2half((obj1 ? fmaxf(v10, 1e-6f) : 1.0f) * mk1);
            g_F[obase + h1 + j0 + r1] = __float2half((obj1 ? fmaxf(v11, 1e-6f) : 1.0f) * mk1);
        }
    }
}

// ================== projection body (128x64 tile, 256 threads) =============
#define PAS 132
#define PBS 68
#define PA_SZ (8 * PAS * 2)
#define PB_SZ (8 * PBS * 2)
#define PROJ_WORDS (2 * PA_SZ + 2 * PB_SZ)
__device__ __forceinline__ void proj_body(
    const float* __restrict__ A, const float* __restrict__ W,
    const float* __restrict__ bias, float* __restrict__ C,
    int m0, int n0, uint32_t* sm, int t)
{
    uint32_t* AP0 = sm;
    uint32_t* BP0 = sm + 2 * PA_SZ;

    int lane = t & 31, wid = t >> 5;
    int wm = (wid & 3) << 5;
    int wn = (wid >> 2) << 5;
    int frow = lane >> 2, fcol = lane & 3;

    int am = t & 127, ak = (t >> 7) << 2;
    int kp = t >> 5;
    int n2 = lane << 1;

    const float* Ap = A + (long long)(m0 + am) * D_;
    const float* Wp = W + n0;

    float acc[2][4][4];
    #pragma unroll
    for (int i = 0; i < 2; i++)
        #pragma unroll
        for (int j = 0; j < 4; j++)
            #pragma unroll
            for (int r = 0; r < 4; r++) acc[i][j][r] = 0.0f;

    float4 a0 = *(const float4*)(Ap + ak);
    float4 a1 = *(const float4*)(Ap + ak + 8);
    float2 w0 = *(const float2*)(Wp + (long long)(2 * kp) * D_ + n2);
    float2 w1 = *(const float2*)(Wp + (long long)(2 * kp + 1) * D_ + n2);

    auto pstore = [&](int BUF) {
        int kw0 = ak >> 1;
        uint32_t* APb = AP0 + BUF * PA_SZ;
        uint32_t* BPb = BP0 + BUF * PB_SZ;
        auto sA = [&](int kw, float e, float o) {
            uint32_t hh = pack_bf(e, o);
            *(uint2*)&APb[2 * (kw * PAS + am)] = make_uint2(hh, resid_bf(e, o, hh));
        };
        sA(kw0,     a0.x, a0.y);
        sA(kw0 + 1, a0.z, a0.w);
        sA(kw0 + 4, a1.x, a1.y);
        sA(kw0 + 5, a1.z, a1.w);
        uint32_t h0 = pack_bf(w0.x, w1.x);
        uint32_t l0 = resid_bf(w0.x, w1.x, h0);
        uint32_t h1 = pack_bf(w0.y, w1.y);
        uint32_t l1 = resid_bf(w0.y, w1.y, h1);
        *(uint4*)&BPb[2 * (kp * PBS + n2)] = make_uint4(h0, l0, h1, l1);
    };

    pstore(0);
    __syncthreads();

    int buf = 0;
    for (int k0 = 0; k0 < D_; k0 += 16) {
        int kn = k0 + 16;
        if (kn < D_) {
            a0 = *(const float4*)(Ap + kn + ak);
            a1 = *(const float4*)(Ap + kn + ak + 8);
            w0 = *(const float2*)(Wp + (long long)(kn + 2 * kp) * D_ + n2);
            w1 = *(const float2*)(Wp + (long long)(kn + 2 * kp + 1) * D_ + n2);
        }
        {
            const uint32_t* APb = AP0 + buf * PA_SZ;
            const uint32_t* BPb = BP0 + buf * PB_SZ;
            uint32_t ah[2][4], al[2][4];
            #pragma unroll
            for (int mt = 0; mt < 2; mt++) {
                int mb = wm + (mt << 4) + frow;
                uint2 u0 = *(const uint2*)&APb[2 * (fcol * PAS + mb)];
                uint2 u1 = *(const uint2*)&APb[2 * (fcol * PAS + mb + 8)];
                uint2 u2 = *(const uint2*)&APb[2 * ((fcol + 4) * PAS + mb)];
                uint2 u3 = *(const uint2*)&APb[2 * ((fcol + 4) * PAS + mb + 8)];
                ah[mt][0] = u0.x; ah[mt][1] = u1.x; ah[mt][2] = u2.x; ah[mt][3] = u3.x;
                al[mt][0] = u0.y; al[mt][1] = u1.y; al[mt][2] = u2.y; al[mt][3] = u3.y;
            }
            uint32_t bh[4][2], bl[4][2];
            #pragma unroll
            for (int nt = 0; nt < 4; nt++) {
                int nb = wn + (nt << 3) + frow;
                uint2 v0 = *(const uint2*)&BPb[2 * (fcol * PBS + nb)];
                uint2 v1 = *(const uint2*)&BPb[2 * ((fcol + 4) * PBS + nb)];
                bh[nt][0] = v0.x; bh[nt][1] = v1.x;
                bl[nt][0] = v0.y; bl[nt][1] = v1.y;
            }
            #pragma unroll
            for (int mt = 0; mt < 2; mt++)
                #pragma unroll
                for (int nt = 0; nt < 4; nt++) {
                    mma_bf16(acc[mt][nt], ah[mt], bh[nt]);
                    mma_bf16(acc[mt][nt], ah[mt], bl[nt]);
                    mma_bf16(acc[mt][nt], al[mt], bh[nt]);
                }
        }
        if (kn < D_) {
            buf ^= 1;
            pstore(buf);
        }
        __syncthreads();
    }

    #pragma unroll
    for (int mt = 0; mt < 2; mt++) {
        int row0 = m0 + wm + (mt << 4) + frow;
        #pragma unroll
        for (int nt = 0; nt < 4; nt++) {
            int col = n0 + wn + (nt << 3) + (fcol << 1);
            float bv0 = bias[col], bv1 = bias[col + 1];
            float2 u0 = make_float2(acc[mt][nt][0] + bv0, acc[mt][nt][1] + bv1);
            float2 u1 = make_float2(acc[mt][nt][2] + bv0, acc[mt][nt][3] + bv1);
            *(float2*)(C + (long long)row0 * D_ + col) = u0;
            *(float2*)(C + (long long)(row0 + 8) * D_ + col) = u1;
        }
    }
}

// ================== fused QKV + geometry launch (interleaved) ==============
// 2816 = 11*256 blocks; within each group of 11, r<3 -> proj (3*256=768),
// r>=3 -> geom (8*256=2048). Every scheduling window mixes both block types.
#define FUSED_SMEM (2 * GEOM_WORDS * 4)
__global__ void __launch_bounds__(256, 2) fused_qkv_geom(
    const float* __restrict__ A0, const float* __restrict__ A1, const float* __restrict__ A2,
    const float* __restrict__ W0, const float* __restrict__ W1, const float* __restrict__ W2,
    const float* __restrict__ b0p, const float* __restrict__ b1p, const float* __restrict__ b2p,
    float* __restrict__ C0, float* __restrict__ C1, float* __restrict__ C2,
    const float* __restrict__ WG, const float* __restrict__ bG,
    const int* __restrict__ msk)
{
    extern __shared__ uint32_t dsm[];
    int bx = blockIdx.x;
    int g = bx / 11, rr = bx - g * 11;
    if (rr < 3) {
        int pb = g * 3 + rr;          // 0..767
        int p = pb >> 8;
        int r = pb & 255;
        int m0 = (r >> 3) << 7, n0 = (r & 7) << 6;
        const float* A = (p == 0) ? A0 : (p == 1) ? A1 : A2;
        const float* W = (p == 0) ? W0 : (p == 1) ? W1 : W2;
        const float* bias = (p == 0) ? b0p : (p == 1) ? b1p : b2p;
        float* C = (p == 0) ? C0 : (p == 1) ? C1 : C2;
        proj_body(A, W, bias, C, m0, n0, dsm, threadIdx.x);
    } else {
        int gx = g * 8 + (rr - 3);    // 0..2047
        int half = threadIdx.x >> 7;
        int row = (gx << 1) | half;
        geom_body(WG, bG, msk, row, threadIdx.x & 127, dsm + half * GEOM_WORDS);
    }
}

// ================== output projection (thin wrapper) =======================
__global__ void __launch_bounds__(256, 2) proj_gemm_single(
    const float* __restrict__ A, const float* __restrict__ W,
    const float* __restrict__ bias, float* __restrict__ C)
{
    extern __shared__ uint32_t dsm[];
    proj_body(A, W, bias, C, (int)(blockIdx.y << 7), (int)(blockIdx.x << 6),
              dsm, threadIdx.x);
}

// ---------------- fused flash attention: BM=128, P in registers (R14) ------
#define FQP 0
#define FKP 8448
#define FVP 16896
#define FRM 25600
#define FLASH_SMEM (25856 * 4)
#define QKS 132
#define VSP 68
#define QSC 0.18033688011111772f   // 0.125 * log2(e)

__global__ void __launch_bounds__(256) flash_kernel() {
    extern __shared__ uint32_t fsm[];
    float* redm = (float*)(fsm + FRM);
    float* OX = (float*)(fsm + FKP);          // O exchange (reuses K area)
    float* LX = (float*)(fsm + FKP + 8192);   // l exchange

    int t = threadIdx.x;
    int lane = t & 31, w = t >> 5;
    int wm = (w & 3) << 5;
    int wn = w >> 2;
    int frow = lane >> 2, fcol = lane & 3;
    int i0 = blockIdx.x << 7;
    int h  = blockIdx.y;
    int b  = blockIdx.z;
    const float* Qg = g_q + (long long)b * N_ * D_ + h * DK_;
    const float* Kg = g_k + (long long)b * N_ * D_ + h * DK_;
    const float* Vg = g_v + (long long)b * N_ * D_ + h * DK_;
    const __half* Fg = g_F + ((long long)(b * H_ + h)) * NN_ + (long long)i0 * N_;
    float* AOg = g_ao + (long long)b * N_ * D_ + h * DK_;

    // ---- load Q planes (pre-scaled by 0.125*log2e) ----
    {
        int qi = t & 127, half = t >> 7;
        const float* src = Qg + (long long)(i0 + qi) * D_;
        #pragma unroll
        for (int it = 0; it < 8; it++) {
            int d0 = half * 32 + it * 4;
            float4 u = *(const float4*)(src + d0);
            u.x *= QSC; u.y *= QSC; u.z *= QSC; u.w *= QSC;
            int kw = d0 >> 1;
            uint32_t h0 = pack_bf(u.x, u.y);
            uint32_t h1 = pack_bf(u.z, u.w);
            *(uint2*)&fsm[FQP + 2 * ((kw + 0) * QKS + qi)] = make_uint2(h0, resid_bf(u.x, u.y, h0));
            *(uint2*)&fsm[FQP + 2 * ((kw + 1) * QKS + qi)] = make_uint2(h1, resid_bf(u.z, u.w, h1));
        }
    }

    float O[2][8][4];
    float m8[2][2], l8[2][2];
    #pragma unroll
    for (int mt = 0; mt < 2; mt++) {
        m8[mt][0] = -1e30f; m8[mt][1] = -1e30f;
        l8[mt][0] = 0.0f;   l8[mt][1] = 0.0f;
        #pragma unroll
        for (int nt = 0; nt < 8; nt++)
            #pragma unroll
            for (int r = 0; r < 4; r++) O[mt][nt][r] = 0.0f;
    }

    #pragma unroll 1
    for (int jt = 0; jt < 4; jt++) {
        int j0 = jt << 7;
        __syncthreads();
        // ---- K planes ----
        {
            int kj = t & 127, half = t >> 7;
            const float* src = Kg + (long long)(j0 + kj) * D_;
            #pragma unroll
            for (int it = 0; it < 8; it++) {
                int d0 = half * 32 + it * 4;
                float4 u = *(const float4*)(src + d0);
                int kw = d0 >> 1;
                uint32_t h0 = pack_bf(u.x, u.y);
                uint32_t h1 = pack_bf(u.z, u.w);
                *(uint2*)&fsm[FKP + 2 * ((kw + 0) * QKS + kj)] = make_uint2(h0, resid_bf(u.x, u.y, h0));
                *(uint2*)&fsm[FKP + 2 * ((kw + 1) * QKS + kj)] = make_uint2(h1, resid_bf(u.z, u.w, h1));
            }
        }
        // ---- V planes: [kword j][col d] ----
        {
            int d4 = (t & 15) << 2;
            int jp0 = t >> 4;
            #pragma unroll
            for (int it = 0; it < 4; it++) {
                int jp = jp0 + it * 16;
                const float* v0p = Vg + (long long)(j0 + 2 * jp) * D_ + d4;
                float4 x = *(const float4*)v0p;
                float4 y = *(const float4*)(v0p + D_);
                uint32_t h0 = pack_bf(x.x, y.x);
                uint32_t l0 = resid_bf(x.x, y.x, h0);
                uint32_t h1 = pack_bf(x.y, y.y);
                uint32_t l1 = resid_bf(x.y, y.y, h1);
                uint32_t h2 = pack_bf(x.z, y.z);
                uint32_t l2 = resid_bf(x.z, y.z, h2);
                uint32_t h3 = pack_bf(x.w, y.w);
                uint32_t l3 = resid_bf(x.w, y.w, h3);
                *(uint4*)&fsm[FVP + 2 * (jp * VSP + d4)]     = make_uint4(h0, l0, h1, l1);
                *(uint4*)&fsm[FVP + 2 * (jp * VSP + d4 + 2)] = make_uint4(h2, l2, h3, l3);
            }
        }
        __syncthreads();

        // ---- S = Q @ K^T (scores in log2 domain) ----
        float S[2][8][4];
        #pragma unroll
        for (int mt = 0; mt < 2; mt++)
            #pragma unroll
            for (int nt = 0; nt < 8; nt++)
                #pragma unroll
                for (int r = 0; r < 4; r++) S[mt][nt][r] = 0.0f;
        #pragma unroll
        for (int ks = 0; ks < 4; ks++) {
            int r0 = (ks * 8 + fcol) * QKS, r1 = (ks * 8 + fcol + 4) * QKS;
            uint32_t ah[2][4], al[2][4];
            #pragma unroll
            for (int mt = 0; mt < 2; mt++) {
                int mb = wm + (mt << 4) + frow;
                uint2 u0 = *(const uint2*)&fsm[FQP + 2 * (r0 + mb)];
                uint2 u1 = *(const uint2*)&fsm[FQP + 2 * (r0 + mb + 8)];
                uint2 u2 = *(const uint2*)&fsm[FQP + 2 * (r1 + mb)];
                uint2 u3 = *(const uint2*)&fsm[FQP + 2 * (r1 + mb + 8)];
                ah[mt][0] = u0.x; ah[mt][1] = u1.x; ah[mt][2] = u2.x; ah[mt][3] = u3.x;
                al[mt][0] = u0.y; al[mt][1] = u1.y; al[mt][2] = u2.y; al[mt][3] = u3.y;
            }
            #pragma unroll
            for (int nt = 0; nt < 8; nt++) {
                int nb = wn * 64 + (nt << 3) + frow;
                uint2 v0 = *(const uint2*)&fsm[FKP + 2 * (r0 + nb)];
                uint2 v1 = *(const uint2*)&fsm[FKP + 2 * (r1 + nb)];
                uint32_t bh[2] = {v0.x, v1.x};
                uint32_t bl[2] = {v0.y, v1.y};
                #pragma unroll
                for (int mt = 0; mt < 2; mt++) {
                    mma_bf16(S[mt][nt], ah[mt], bh);
                    mma_bf16(S[mt][nt], ah[mt], bl);
                    mma_bf16(S[mt][nt], al[mt], bh);
                }
            }
        }

        // ---- row max (shared across wn pair for consistent shift) ----
        float mx[2][2];
        #pragma unroll
        for (int mt = 0; mt < 2; mt++) {
            float a = -1e30f, c2 = -1e30f;
            #pragma unroll
            for (int nt = 0; nt < 8; nt++) {
                a  = fmaxf(a,  fmaxf(S[mt][nt][0], S[mt][nt][1]));
                c2 = fmaxf(c2, fmaxf(S[mt][nt][2], S[mt][nt][3]));
            }
            a  = fmaxf(a,  __shfl_xor_sync(0xffffffffu, a, 1));
            a  = fmaxf(a,  __shfl_xor_sync(0xffffffffu, a, 2));
            c2 = fmaxf(c2, __shfl_xor_sync(0xffffffffu, c2, 1));
            c2 = fmaxf(c2, __shfl_xor_sync(0xffffffffu, c2, 2));
            mx[mt][0] = a; mx[mt][1] = c2;
        }
        if (fcol == 0) {
            #pragma unroll
            for (int mt = 0; mt < 2; mt++) {
                int rl = wm + (mt << 4) + frow;
                redm[wn * 128 + rl] = mx[mt][0];
                redm[wn * 128 + rl + 8] = mx[mt][1];
            }
        }
        __syncthreads();
        float mnew[2][2];
        #pragma unroll
        for (int mt = 0; mt < 2; mt++) {
            int rl = wm + (mt << 4) + frow;
            float f0 = fmaxf(mx[mt][0], redm[(1 ^ wn) * 128 + rl]);
            float f1 = fmaxf(mx[mt][1], redm[(1 ^ wn) * 128 + rl + 8]);
            mnew[mt][0] = fmaxf(m8[mt][0], f0);
            mnew[mt][1] = fmaxf(m8[mt][1], f1);
            float fa0 = fex2(m8[mt][0] - mnew[mt][0]);
            float fa1 = fex2(m8[mt][1] - mnew[mt][1]);
            m8[mt][0] = mnew[mt][0]; m8[mt][1] = mnew[mt][1];
            l8[mt][0] *= fa0; l8[mt][1] *= fa1;
            #pragma unroll
            for (int nt = 0; nt < 8; nt++) {
                O[mt][nt][0] *= fa0; O[mt][nt][1] *= fa0;
                O[mt][nt][2] *= fa1; O[mt][nt][3] *= fa1;
            }
        }

        // ---- p = F' * 2^(s - m), kept in registers; accumulate partial l ----
        #pragma unroll
        for (int mt = 0; mt < 2; mt++) {
            int rl = wm + (mt << 4) + frow;
            #pragma unroll
            for (int nt = 0; nt < 8; nt++) {
                const __half* fp = Fg + (long long)rl * N_ + j0 + wn * 64 + (nt << 3) + (fcol << 1);
                float2 f0 = __half22float2(*(const __half2*)fp);
                float2 f1 = __half22float2(*(const __half2*)(fp + 8 * N_));
                float p0 = f0.x * fex2(S[mt][nt][0] - mnew[mt][0]);
                float p1 = f0.y * fex2(S[mt][nt][1] - mnew[mt][0]);
                float p2 = f1.x * fex2(S[mt][nt][2] - mnew[mt][1]);
                float p3 = f1.y * fex2(S[mt][nt][3] - mnew[mt][1]);
                l8[mt][0] += p0 + p1;
                l8[mt][1] += p2 + p3;
                S[mt][nt][0] = p0; S[mt][nt][1] = p1;
                S[mt][nt][2] = p2; S[mt][nt][3] = p3;
            }
        }

        // ---- O += P @ V  (A-operand packed from S registers; warp's j-half) ----
        #pragma unroll
        for (int ks = 0; ks < 4; ks++) {
            uint32_t ah[2][4], al[2][4];
            #pragma unroll
            for (int mt = 0; mt < 2; mt++) {
                ah[mt][0] = pack_bf(S[mt][2*ks][0],   S[mt][2*ks][1]);
                ah[mt][1] = pack_bf(S[mt][2*ks][2],   S[mt][2*ks][3]);
                ah[mt][2] = pack_bf(S[mt][2*ks+1][0], S[mt][2*ks+1][1]);
                ah[mt][3] = pack_bf(S[mt][2*ks+1][2], S[mt][2*ks+1][3]);
                al[mt][0] = resid_bf(S[mt][2*ks][0],   S[mt][2*ks][1],   ah[mt][0]);
                al[mt][1] = resid_bf(S[mt][2*ks][2],   S[mt][2*ks][3],   ah[mt][1]);
                al[mt][2] = resid_bf(S[mt][2*ks+1][0], S[mt][2*ks+1][1], ah[mt][2]);
                al[mt][3] = resid_bf(S[mt][2*ks+1][2], S[mt][2*ks+1][3], ah[mt][3]);
            }
            int r0v = (wn * 32 + ks * 8 + fcol) * VSP;
            int r1v = (wn * 32 + ks * 8 + fcol + 4) * VSP;
            #pragma unroll
            for (int nt = 0; nt < 8; nt++) {
                int nb = (nt << 3) + frow;
                uint2 v0 = *(const uint2*)&fsm[FVP + 2 * (r0v + nb)];
                uint2 v1 = *(const uint2*)&fsm[FVP + 2 * (r1v + nb)];
                uint32_t bh[2] = {v0.x, v1.x};
                uint32_t bl[2] = {v0.y, v1.y};
                #pragma unroll
                for (int mt = 0; mt < 2; mt++) {
                    mma_bf16(O[mt][nt], ah[mt], bh);
                    mma_bf16(O[mt][nt], al[mt], bh);
                    mma_bf16(O[mt][nt], ah[mt], bl);
                }
            }
        }
    }

    // ---- final reduction: quad-reduce l; sum O/l across wn pair ----
    #pragma unroll
    for (int mt = 0; mt < 2; mt++) {
        l8[mt][0] += __shfl_xor_sync(0xffffffffu, l8[mt][0], 1);
        l8[mt][0] += __shfl_xor_sync(0xffffffffu, l8[mt][0], 2);
        l8[mt][1] += __shfl_xor_sync(0xffffffffu, l8[mt][1], 1);
        l8[mt][1] += __shfl_xor_sync(0xffffffffu, l8[mt][1], 2);
    }
    __syncthreads();
    if (wn == 1) {
        #pragma unroll
        for (int mt = 0; mt < 2; mt++) {
            int rl = wm + (mt << 4) + frow;
            #pragma unroll
            for (int nt = 0; nt < 8; nt++) {
                int col = (nt << 3) + (fcol << 1);
                *(float2*)&OX[rl * 64 + col]       = make_float2(O[mt][nt][0], O[mt][nt][1]);
                *(float2*)&OX[(rl + 8) * 64 + col] = make_float2(O[mt][nt][2], O[mt][nt][3]);
            }
            if (fcol == 0) {
                LX[rl] = l8[mt][0];
                LX[rl + 8] = l8[mt][1];
            }
        }
    }
    __syncthreads();
    if (wn == 0) {
        #pragma unroll
        for (int mt = 0; mt < 2; mt++) {
            int rl = wm + (mt << 4) + frow;
            float inv0 = 1.0f / (l8[mt][0] + LX[rl]);
            float inv1 = 1.0f / (l8[mt][1] + LX[rl + 8]);
            #pragma unroll
            for (int nt = 0; nt < 8; nt++) {
                int col = (nt << 3) + (fcol << 1);
                float2 x0 = *(const float2*)&OX[rl * 64 + col];
                float2 x1 = *(const float2*)&OX[(rl + 8) * 64 + col];
                float2 u0 = make_float2((O[mt][nt][0] + x0.x) * inv0,
                                        (O[mt][nt][1] + x0.y) * inv0);
                float2 u1 = make_float2((O[mt][nt][2] + x1.x) * inv1,
                                        (O[mt][nt][3] + x1.y) * inv1);
                *(float2*)(AOg + (long long)(i0 + rl) * D_ + col) = u0;
                *(float2*)(AOg + (long long)(i0 + rl + 8) * D_ + col) = u1;
            }
        }
    }
}

// ---------------- launch ----------------------------------------------------
extern "C" void kernel_launch(void* const* d_in, const int* in_sizes, int n_in,
                              void* d_out, int out_size) {
    const float* inq = (const float*)d_in[0];
    const float* ink = (const float*)d_in[1];
    const float* inv = (const float*)d_in[2];
    const float* box = (const float*)d_in[3];
    const int*   msk = (const int*)d_in[4];
    const void*  nob = d_in[5];
    const float* Wq = (const float*)d_in[6];  const float* bq = (const float*)d_in[7];
    const float* Wk = (const float*)d_in[8];  const float* bk = (const float*)d_in[9];
    const float* Wv = (const float*)d_in[10]; const float* bv = (const float*)d_in[11];
    const float* Wo = (const float*)d_in[12]; const float* bo = (const float*)d_in[13];
    const float* WG = (const float*)d_in[14]; const float* bG = (const float*)d_in[15];
    float* out = (float*)d_out;

    float *pq, *pk, *pv, *pao;
    cudaGetSymbolAddress((void**)&pq,  g_q);
    cudaGetSymbolAddress((void**)&pk,  g_k);
    cudaGetSymbolAddress((void**)&pv,  g_v);
    cudaGetSymbolAddress((void**)&pao, g_ao);

    cudaFuncSetAttribute(flash_kernel, cudaFuncAttributeMaxDynamicSharedMemorySize, FLASH_SMEM);
    cudaFuncSetAttribute(fused_qkv_geom, cudaFuncAttributeMaxDynamicSharedMemorySize, FUSED_SMEM);

    box_pre<<<32, 128>>>(box, nob);

    fused_qkv_geom<<<2816, 256, FUSED_SMEM>>>(
        inq, ink, inv, Wq, Wk, Wv, bq, bk, bv, pq, pk, pv, WG, bG, msk);

    flash_kernel<<<dim3(4, H_, B_), 256, FLASH_SMEM>>>();

    dim3 gO(8, 32, 1);
    proj_gemm_single<<<gO, 256, PROJ_WORDS * 4>>>(pao, Wo, bo, out);
}

// round 17
// speedup vs baseline: 1.0769x; 1.0769x over previous
#include <cuda_runtime.h>
#include <cuda_fp16.h>
#include <math.h>
#include <stdint.h>

#define B_ 8
#define N_ 512
#define D_ 512
#define H_ 8
#define DK_ 64
#define BNT 4096                 // B*N
#define NN_ 262144               // N*N

// ---------------- scratch (static device globals; no allocation allowed) ----
__device__ float g_q [BNT * D_];
__device__ float g_k [BNT * D_];
__device__ float g_v [BNT * D_];
__device__ float g_ao[BNT * D_];
__device__ __half g_F [(long long)B_ * H_ * NN_];  // geometry factor * mask, fp16
__device__ float g_cx[BNT], g_cy[BNT], g_iw[BNT], g_ih[BNT], g_no[BNT];
__device__ float g_tw[32][BNT];   // per-box sin/cos tables

// 100 / 1000^(m/8)
__constant__ float c_DM[8] = {
    100.0f, 42.169650342858224f, 17.78279410038923f, 7.498942093324559f,
    3.1622776601683795f, 1.3335214321633242f, 0.5623413251903491f, 0.23713737056616555f};

// Cody-Waite reduced fast sincos
__device__ __forceinline__ void fsincos(float x, float& s, float& c) {
    float k = rintf(x * 0.15915494309189535f);
    float r = __fmaf_rn(k, -6.28125f, x);
    r = __fmaf_rn(k, -1.9353071795864769e-3f, r);
    s = __sinf(r);
    c = __cosf(r);
}

__device__ __forceinline__ float fex2(float x) {
    float r;
    asm("ex2.approx.f32 %0, %1;" : "=f"(r) : "f"(x));
    return r;
}

// ---------------- per-box precompute (detect folded in) ---------------------
__global__ void box_pre(const float* __restrict__ box, const void* __restrict__ nobj) {
    int t = threadIdx.x;
    int i = blockIdx.x * blockDim.x + t;
    int v = 0;
    for (int k = t; k < 1024; k += blockDim.x) {
        int x = ((const int*)nobj)[k];
        v |= (x != 0 && x != 1);
    }
    int isbyte = __syncthreads_or(v);
    if (i >= BNT) return;
    float x0 = box[4*i+0], y0 = box[4*i+1], x1 = box[4*i+2], y1 = box[4*i+3];
    float w = x1 - x0 + 1.0f, h = y1 - y0 + 1.0f;
    g_cx[i] = 0.5f * (x0 + x1);
    g_cy[i] = 0.5f * (y0 + y1);
    g_iw[i] = 1.0f / w;
    g_ih[i] = 1.0f / h;
    float lw = logf(w), lh = logf(h);
    #pragma unroll
    for (int m = 0; m < 8; m++) {
        float s, c;
        fsincos(c_DM[m] * lw, s, c);
        g_tw[m][i] = s;      g_tw[8 + m][i] = c;
        fsincos(c_DM[m] * lh, s, c);
        g_tw[16 + m][i] = s; g_tw[24 + m][i] = c;
    }
    int nv = isbyte ? (int)((const unsigned char*)nobj)[i]
                    : ((const int*)nobj)[i];
    g_no[i] = nv ? 1.0f : 0.0f;
}

// ---------------- BF16 2-plane helpers --------------------------------------
__device__ __forceinline__ uint32_t pack_bf(float e, float o) {
    uint32_t r;
    asm("cvt.rn.bf16x2.f32 %0, %1, %2;" : "=r"(r) : "f"(o), "f"(e));
    return r;
}
__device__ __forceinline__ uint32_t resid_bf(float e, float o, uint32_t hw) {
    float eh = __uint_as_float(hw << 16);
    float oh = __uint_as_float(hw & 0xffff0000u);
    return pack_bf(e - eh, o - oh);
}
__device__ __forceinline__ void mma_bf16(float* d, const uint32_t* a, const uint32_t* b) {
    asm("mma.sync.aligned.m16n8k16.row.col.f32.bf16.bf16.f32 "
        "{%0,%1,%2,%3}, {%4,%5,%6,%7}, {%8,%9}, {%0,%1,%2,%3};"
        : "+f"(d[0]), "+f"(d[1]), "+f"(d[2]), "+f"(d[3])
        : "r"(a[0]), "r"(a[1]), "r"(a[2]), "r"(a[3]), "r"(b[0]), "r"(b[1]));
}

// ================== geometry body (one (b,i) row, 128 threads) =============
#define GES 132
#define GEOM_WORDS (2 * 32 * GES)
__device__ __forceinline__ void geom_body(
    const float* __restrict__ WG, const float* __restrict__ bG,
    const int* __restrict__ msk, int row, int t, uint32_t* EP)
{
    int lane = t & 31, w = t >> 5;
    int frow = lane >> 2, fcol = lane & 3;
    int b = row >> 9, i = row & 511;
    int base = b << 9;
    int gi = base + i;
    float cxi = g_cx[gi], cyi = g_cy[gi], iwi = g_iw[gi], ihi = g_ih[gi];
    float noi = g_no[gi];
    const int* mrow = msk + b * N_;
    float swiW[8], cwiW[8], swiH[8], cwiH[8];
    #pragma unroll
    for (int m = 0; m < 8; m++) {
        swiW[m] = g_tw[m][gi];      cwiW[m] = g_tw[8 + m][gi];
        swiH[m] = g_tw[16 + m][gi]; cwiH[m] = g_tw[24 + m][gi];
    }
    uint32_t wbh[4][2], wbl[4][2];
    #pragma unroll
    for (int ks = 0; ks < 4; ks++) {
        float b00 = WG[frow * 64 + ks * 16 + 2 * fcol];
        float b01 = WG[frow * 64 + ks * 16 + 2 * fcol + 1];
        float b10 = WG[frow * 64 + ks * 16 + 2 * fcol + 8];
        float b11 = WG[frow * 64 + ks * 16 + 2 * fcol + 9];
        wbh[ks][0] = pack_bf(b00, b01); wbl[ks][0] = resid_bf(b00, b01, wbh[ks][0]);
        wbh[ks][1] = pack_bf(b10, b11); wbl[ks][1] = resid_bf(b10, b11, wbh[ks][1]);
    }
    float bg0 = bG[2 * fcol], bg1 = bG[2 * fcol + 1];
    long long obase = (long long)b * H_ * NN_ + (long long)i * N_;

    auto est = [&](int kw, float a, float bvv) {
        uint32_t hh = pack_bf(a, bvv);
        *(uint2*)&EP[2 * (kw * GES + t)] = make_uint2(hh, resid_bf(a, bvv, hh));
    };

    for (int jt = 0; jt < 4; jt++) {
        int j0 = jt << 7;
        int jj = base + j0 + t;
        __syncthreads();
        float dx = __logf(fmaxf(fabsf(g_cx[jj] - cxi) * iwi, 1e-3f));
        float dy = __logf(fmaxf(fabsf(g_cy[jj] - cyi) * ihi, 1e-3f));
        #pragma unroll
        for (int mp = 0; mp < 4; mp++) {
            int m0 = 2 * mp, m1 = m0 + 1;
            float s0, c0, s1, c1;
            fsincos(dx * c_DM[m0], s0, c0);
            fsincos(dx * c_DM[m1], s1, c1);
            est(mp, s0, s1); est(16 + mp, c0, c1);
            fsincos(dy * c_DM[m0], s0, c0);
            fsincos(dy * c_DM[m1], s1, c1);
            est(4 + mp, s0, s1); est(20 + mp, c0, c1);
            float swj0 = g_tw[m0][jj], cwj0 = g_tw[8 + m0][jj];
            float swj1 = g_tw[m1][jj], cwj1 = g_tw[8 + m1][jj];
            est(8 + mp,  swiW[m0]*cwj0 - cwiW[m0]*swj0, swiW[m1]*cwj1 - cwiW[m1]*swj1);
            est(24 + mp, cwiW[m0]*cwj0 + swiW[m0]*swj0, cwiW[m1]*cwj1 + swiW[m1]*swj1);
            float shj0 = g_tw[16 + m0][jj], chj0 = g_tw[24 + m0][jj];
            float shj1 = g_tw[16 + m1][jj], chj1 = g_tw[24 + m1][jj];
            est(12 + mp, swiH[m0]*chj0 - cwiH[m0]*shj0, swiH[m1]*chj1 - cwiH[m1]*shj1);
            est(28 + mp, cwiH[m0]*chj0 + swiH[m0]*shj0, cwiH[m1]*chj1 + swiH[m1]*shj1);
        }
        __syncthreads();
        float acc[2][4];
        #pragma unroll
        for (int mt = 0; mt < 2; mt++)
            #pragma unroll
            for (int r = 0; r < 4; r++) acc[mt][r] = 0.0f;
        #pragma unroll
        for (int ks = 0; ks < 4; ks++) {
            #pragma unroll
            for (int mt = 0; mt < 2; mt++) {
                int p = (w << 5) + (mt << 4) + frow;
                uint2 u0 = *(const uint2*)&EP[2 * ((ks*8 + fcol) * GES + p)];
                uint2 u1 = *(const uint2*)&EP[2 * ((ks*8 + fcol) * GES + p + 8)];
                uint2 u2 = *(const uint2*)&EP[2 * ((ks*8 + fcol + 4) * GES + p)];
                uint2 u3 = *(const uint2*)&EP[2 * ((ks*8 + fcol + 4) * GES + p + 8)];
                uint32_t ah[4] = {u0.x, u1.x, u2.x, u3.x};
                uint32_t al[4] = {u0.y, u1.y, u2.y, u3.y};
                mma_bf16(acc[mt], ah, wbh[ks]);
                mma_bf16(acc[mt], ah, wbl[ks]);
                mma_bf16(acc[mt], al, wbh[ks]);
            }
        }
        #pragma unroll
        for (int mt = 0; mt < 2; mt++) {
            int r0 = (w << 5) + (mt << 4) + frow;
            int r1 = r0 + 8;
            bool obj0 = (fmaxf(noi, g_no[base + j0 + r0]) < 0.5f);
            bool obj1 = (fmaxf(noi, g_no[base + j0 + r1]) < 0.5f);
            float mk0 = mrow[j0 + r0] ? 1.0f : 0.0f;
            float mk1 = mrow[j0 + r1] ? 1.0f : 0.0f;
            float v00 = acc[mt][0] + bg0, v01 = acc[mt][1] + bg1;
            float v10 = acc[mt][2] + bg0, v11 = acc[mt][3] + bg1;
            long long h0 = (long long)(2 * fcol) * NN_;
            long long h1 = h0 + NN_;
            g_F[obase + h0 + j0 + r0] = __float2half((obj0 ? fmaxf(v00, 1e-6f) : 1.0f) * mk0);
            g_F[obase + h1 + j0 + r0] = __float2half((obj0 ? fmaxf(v01, 1e-6f) : 1.0f) * mk0);
            g_F[obase + h0 + j0 + r1] = __float2half((obj1 ? fmaxf(v10, 1e-6f) : 1.0f) * mk1);
            g_F[obase + h1 + j0 + r1] = __float2half((obj1 ? fmaxf(v11, 1e-6f) : 1.0f) * mk1);
        }
    }
}

// ================== projection body (128x64 tile, 256 threads) =============
#define PAS 132
#define PBS 68
#define PA_SZ (8 * PAS * 2)
#define PB_SZ (8 * PBS * 2)
#define PROJ_WORDS (2 * PA_SZ + 2 * PB_SZ)
__device__ __forceinline__ void proj_body(
    const float* __restrict__ A, const float* __restrict__ W,
    const float* __restrict__ bias, float* __restrict__ C,
    int m0, int n0, uint32_t* sm, int t)
{
    uint32_t* AP0 = sm;
    uint32_t* BP0 = sm + 2 * PA_SZ;

    int lane = t & 31, wid = t >> 5;
    int wm = (wid & 3) << 5;
    int wn = (wid >> 2) << 5;
    int frow = lane >> 2, fcol = lane & 3;

    int am = t & 127, ak = (t >> 7) << 2;
    int kp = t >> 5;
    int n2 = lane << 1;

    const float* Ap = A + (long long)(m0 + am) * D_;
    const float* Wp = W + n0;

    float acc[2][4][4];
    #pragma unroll
    for (int i = 0; i < 2; i++)
        #pragma unroll
        for (int j = 0; j < 4; j++)
            #pragma unroll
            for (int r = 0; r < 4; r++) acc[i][j][r] = 0.0f;

    float4 a0 = *(const float4*)(Ap + ak);
    float4 a1 = *(const float4*)(Ap + ak + 8);
    float2 w0 = *(const float2*)(Wp + (long long)(2 * kp) * D_ + n2);
    float2 w1 = *(const float2*)(Wp + (long long)(2 * kp + 1) * D_ + n2);

    auto pstore = [&](int BUF) {
        int kw0 = ak >> 1;
        uint32_t* APb = AP0 + BUF * PA_SZ;
        uint32_t* BPb = BP0 + BUF * PB_SZ;
        auto sA = [&](int kw, float e, float o) {
            uint32_t hh = pack_bf(e, o);
            *(uint2*)&APb[2 * (kw * PAS + am)] = make_uint2(hh, resid_bf(e, o, hh));
        };
        sA(kw0,     a0.x, a0.y);
        sA(kw0 + 1, a0.z, a0.w);
        sA(kw0 + 4, a1.x, a1.y);
        sA(kw0 + 5, a1.z, a1.w);
        uint32_t h0 = pack_bf(w0.x, w1.x);
        uint32_t l0 = resid_bf(w0.x, w1.x, h0);
        uint32_t h1 = pack_bf(w0.y, w1.y);
        uint32_t l1 = resid_bf(w0.y, w1.y, h1);
        *(uint4*)&BPb[2 * (kp * PBS + n2)] = make_uint4(h0, l0, h1, l1);
    };

    pstore(0);
    __syncthreads();

    int buf = 0;
    for (int k0 = 0; k0 < D_; k0 += 16) {
        int kn = k0 + 16;
        if (kn < D_) {
            a0 = *(const float4*)(Ap + kn + ak);
            a1 = *(const float4*)(Ap + kn + ak + 8);
            w0 = *(const float2*)(Wp + (long long)(kn + 2 * kp) * D_ + n2);
            w1 = *(const float2*)(Wp + (long long)(kn + 2 * kp + 1) * D_ + n2);
        }
        {
            const uint32_t* APb = AP0 + buf * PA_SZ;
            const uint32_t* BPb = BP0 + buf * PB_SZ;
            uint32_t ah[2][4], al[2][4];
            #pragma unroll
            for (int mt = 0; mt < 2; mt++) {
                int mb = wm + (mt << 4) + frow;
                uint2 u0 = *(const uint2*)&APb[2 * (fcol * PAS + mb)];
                uint2 u1 = *(const uint2*)&APb[2 * (fcol * PAS + mb + 8)];
                uint2 u2 = *(const uint2*)&APb[2 * ((fcol + 4) * PAS + mb)];
                uint2 u3 = *(const uint2*)&APb[2 * ((fcol + 4) * PAS + mb + 8)];
                ah[mt][0] = u0.x; ah[mt][1] = u1.x; ah[mt][2] = u2.x; ah[mt][3] = u3.x;
                al[mt][0] = u0.y; al[mt][1] = u1.y; al[mt][2] = u2.y; al[mt][3] = u3.y;
            }
            uint32_t bh[4][2], bl[4][2];
            #pragma unroll
            for (int nt = 0; nt < 4; nt++) {
                int nb = wn + (nt << 3) + frow;
                uint2 v0 = *(const uint2*)&BPb[2 * (fcol * PBS + nb)];
                uint2 v1 = *(const uint2*)&BPb[2 * ((fcol + 4) * PBS + nb)];
                bh[nt][0] = v0.x; bh[nt][1] = v1.x;
                bl[nt][0] = v0.y; bl[nt][1] = v1.y;
            }
            #pragma unroll
            for (int mt = 0; mt < 2; mt++)
                #pragma unroll
                for (int nt = 0; nt < 4; nt++) {
                    mma_bf16(acc[mt][nt], ah[mt], bh[nt]);
                    mma_bf16(acc[mt][nt], ah[mt], bl[nt]);
                    mma_bf16(acc[mt][nt], al[mt], bh[nt]);
                }
        }
        if (kn < D_) {
            buf ^= 1;
            pstore(buf);
        }
        __syncthreads();
    }

    #pragma unroll
    for (int mt = 0; mt < 2; mt++) {
        int row0 = m0 + wm + (mt << 4) + frow;
        #pragma unroll
        for (int nt = 0; nt < 4; nt++) {
            int col = n0 + wn + (nt << 3) + (fcol << 1);
            float bv0 = bias[col], bv1 = bias[col + 1];
            float2 u0 = make_float2(acc[mt][nt][0] + bv0, acc[mt][nt][1] + bv1);
            float2 u1 = make_float2(acc[mt][nt][2] + bv0, acc[mt][nt][3] + bv1);
            *(float2*)(C + (long long)row0 * D_ + col) = u0;
            *(float2*)(C + (long long)(row0 + 8) * D_ + col) = u1;
        }
    }
}

// ================== fused QKV + geometry launch (sequential order) =========
#define PROJ_BLOCKS 768
#define FUSED_SMEM (2 * GEOM_WORDS * 4)
__global__ void __launch_bounds__(256, 2) fused_qkv_geom(
    const float* __restrict__ A0, const float* __restrict__ A1, const float* __restrict__ A2,
    const float* __restrict__ W0, const float* __restrict__ W1, const float* __restrict__ W2,
    const float* __restrict__ b0p, const float* __restrict__ b1p, const float* __restrict__ b2p,
    float* __restrict__ C0, float* __restrict__ C1, float* __restrict__ C2,
    const float* __restrict__ WG, const float* __restrict__ bG,
    const int* __restrict__ msk)
{
    extern __shared__ uint32_t dsm[];
    int bx = blockIdx.x;
    if (bx < PROJ_BLOCKS) {
        int p = bx >> 8;
        int r = bx & 255;
        int m0 = (r >> 3) << 7, n0 = (r & 7) << 6;
        const float* A = (p == 0) ? A0 : (p == 1) ? A1 : A2;
        const float* W = (p == 0) ? W0 : (p == 1) ? W1 : W2;
        const float* bias = (p == 0) ? b0p : (p == 1) ? b1p : b2p;
        float* C = (p == 0) ? C0 : (p == 1) ? C1 : C2;
        proj_body(A, W, bias, C, m0, n0, dsm, threadIdx.x);
    } else {
        int gx = bx - PROJ_BLOCKS;
        int half = threadIdx.x >> 7;
        int row = (gx << 1) | half;
        geom_body(WG, bG, msk, row, threadIdx.x & 127, dsm + half * GEOM_WORDS);
    }
}

// ================== output projection (thin wrapper) =======================
__global__ void __launch_bounds__(256, 2) proj_gemm_single(
    const float* __restrict__ A, const float* __restrict__ W,
    const float* __restrict__ bias, float* __restrict__ C)
{
    extern __shared__ uint32_t dsm[];
    proj_body(A, W, bias, C, (int)(blockIdx.y << 7), (int)(blockIdx.x << 6),
              dsm, threadIdx.x);
}

// ---------------- fused flash attention: BM=128, P in registers ------------
// Each j-half (wn) runs an INDEPENDENT online softmax (own m,l,O); halves
// merged once at the end via split-softmax identity. Removes the per-tile
// cross-half max exchange and its __syncthreads (2 syncs/tile instead of 3).
#define FQP 0
#define FKP 8448
#define FVP 16896
#define FLASH_SMEM (25600 * 4)
#define QKS 132
#define VSP 68
#define QSC 0.18033688011111772f   // 0.125 * log2(e)

__global__ void __launch_bounds__(256) flash_kernel() {
    extern __shared__ uint32_t fsm[];
    float* OX = (float*)(fsm + FKP);          // O exchange (reuses K area)
    float* LX = (float*)(fsm + FKP + 8192);   // l exchange (128 floats)
    float* MX = (float*)(fsm + FKP + 8320);   // m exchange (128 floats)

    int t = threadIdx.x;
    int lane = t & 31, w = t >> 5;
    int wm = (w & 3) << 5;
    int wn = w >> 2;
    int frow = lane >> 2, fcol = lane & 3;
    int i0 = blockIdx.x << 7;
    int h  = blockIdx.y;
    int b  = blockIdx.z;
    const float* Qg = g_q + (long long)b * N_ * D_ + h * DK_;
    const float* Kg = g_k + (long long)b * N_ * D_ + h * DK_;
    const float* Vg = g_v + (long long)b * N_ * D_ + h * DK_;
    const __half* Fg = g_F + ((long long)(b * H_ + h)) * NN_ + (long long)i0 * N_;
    float* AOg = g_ao + (long long)b * N_ * D_ + h * DK_;

    // ---- load Q planes (pre-scaled by 0.125*log2e) ----
    {
        int qi = t & 127, half = t >> 7;
        const float* src = Qg + (long long)(i0 + qi) * D_;
        #pragma unroll
        for (int it = 0; it < 8; it++) {
            int d0 = half * 32 + it * 4;
            float4 u = *(const float4*)(src + d0);
            u.x *= QSC; u.y *= QSC; u.z *= QSC; u.w *= QSC;
            int kw = d0 >> 1;
            uint32_t h0 = pack_bf(u.x, u.y);
            uint32_t h1 = pack_bf(u.z, u.w);
            *(uint2*)&fsm[FQP + 2 * ((kw + 0) * QKS + qi)] = make_uint2(h0, resid_bf(u.x, u.y, h0));
            *(uint2*)&fsm[FQP + 2 * ((kw + 1) * QKS + qi)] = make_uint2(h1, resid_bf(u.z, u.w, h1));
        }
    }

    float O[2][8][4];
    float m8[2][2], l8[2][2];
    #pragma unroll
    for (int mt = 0; mt < 2; mt++) {
        m8[mt][0] = -1e30f; m8[mt][1] = -1e30f;
        l8[mt][0] = 0.0f;   l8[mt][1] = 0.0f;
        #pragma unroll
        for (int nt = 0; nt < 8; nt++)
            #pragma unroll
            for (int r = 0; r < 4; r++) O[mt][nt][r] = 0.0f;
    }

    #pragma unroll 1
    for (int jt = 0; jt < 4; jt++) {
        int j0 = jt << 7;
        __syncthreads();   // prev tile's S/PV done before overwriting K/V
        // ---- K planes ----
        {
            int kj = t & 127, half = t >> 7;
            const float* src = Kg + (long long)(j0 + kj) * D_;
            #pragma unroll
            for (int it = 0; it < 8; it++) {
                int d0 = half * 32 + it * 4;
                float4 u = *(const float4*)(src + d0);
                int kw = d0 >> 1;
                uint32_t h0 = pack_bf(u.x, u.y);
                uint32_t h1 = pack_bf(u.z, u.w);
                *(uint2*)&fsm[FKP + 2 * ((kw + 0) * QKS + kj)] = make_uint2(h0, resid_bf(u.x, u.y, h0));
                *(uint2*)&fsm[FKP + 2 * ((kw + 1) * QKS + kj)] = make_uint2(h1, resid_bf(u.z, u.w, h1));
            }
        }
        // ---- V planes: [kword j][col d] ----
        {
            int d4 = (t & 15) << 2;
            int jp0 = t >> 4;
            #pragma unroll
            for (int it = 0; it < 4; it++) {
                int jp = jp0 + it * 16;
                const float* v0p = Vg + (long long)(j0 + 2 * jp) * D_ + d4;
                float4 x = *(const float4*)v0p;
                float4 y = *(const float4*)(v0p + D_);
                uint32_t h0 = pack_bf(x.x, y.x);
                uint32_t l0 = resid_bf(x.x, y.x, h0);
                uint32_t h1 = pack_bf(x.y, y.y);
                uint32_t l1 = resid_bf(x.y, y.y, h1);
                uint32_t h2 = pack_bf(x.z, y.z);
                uint32_t l2 = resid_bf(x.z, y.z, h2);
                uint32_t h3 = pack_bf(x.w, y.w);
                uint32_t l3 = resid_bf(x.w, y.w, h3);
                *(uint4*)&fsm[FVP + 2 * (jp * VSP + d4)]     = make_uint4(h0, l0, h1, l1);
                *(uint4*)&fsm[FVP + 2 * (jp * VSP + d4 + 2)] = make_uint4(h2, l2, h3, l3);
            }
        }
        __syncthreads();

        // ---- S = Q @ K^T (scores in log2 domain) ----
        float S[2][8][4];
        #pragma unroll
        for (int mt = 0; mt < 2; mt++)
            #pragma unroll
            for (int nt = 0; nt < 8; nt++)
                #pragma unroll
                for (int r = 0; r < 4; r++) S[mt][nt][r] = 0.0f;
        #pragma unroll
        for (int ks = 0; ks < 4; ks++) {
            int r0 = (ks * 8 + fcol) * QKS, r1 = (ks * 8 + fcol + 4) * QKS;
            uint32_t ah[2][4], al[2][4];
            #pragma unroll
            for (int mt = 0; mt < 2; mt++) {
                int mb = wm + (mt << 4) + frow;
                uint2 u0 = *(const uint2*)&fsm[FQP + 2 * (r0 + mb)];
                uint2 u1 = *(const uint2*)&fsm[FQP + 2 * (r0 + mb + 8)];
                uint2 u2 = *(const uint2*)&fsm[FQP + 2 * (r1 + mb)];
                uint2 u3 = *(const uint2*)&fsm[FQP + 2 * (r1 + mb + 8)];
                ah[mt][0] = u0.x; ah[mt][1] = u1.x; ah[mt][2] = u2.x; ah[mt][3] = u3.x;
                al[mt][0] = u0.y; al[mt][1] = u1.y; al[mt][2] = u2.y; al[mt][3] = u3.y;
            }
            #pragma unroll
            for (int nt = 0; nt < 8; nt++) {
                int nb = wn * 64 + (nt << 3) + frow;
                uint2 v0 = *(const uint2*)&fsm[FKP + 2 * (r0 + nb)];
                uint2 v1 = *(const uint2*)&fsm[FKP + 2 * (r1 + nb)];
                uint32_t bh[2] = {v0.x, v1.x};
                uint32_t bl[2] = {v0.y, v1.y};
                #pragma unroll
                for (int mt = 0; mt < 2; mt++) {
                    mma_bf16(S[mt][nt], ah[mt], bh);
                    mma_bf16(S[mt][nt], ah[mt], bl);
                    mma_bf16(S[mt][nt], al[mt], bh);
                }
            }
        }

        // ---- per-half row max (warp-local quad reduce only; no sync) ----
        float mnew[2][2];
        #pragma unroll
        for (int mt = 0; mt < 2; mt++) {
            float a = -1e30f, c2 = -1e30f;
            #pragma unroll
            for (int nt = 0; nt < 8; nt++) {
                a  = fmaxf(a,  fmaxf(S[mt][nt][0], S[mt][nt][1]));
                c2 = fmaxf(c2, fmaxf(S[mt][nt][2], S[mt][nt][3]));
            }
            a  = fmaxf(a,  __shfl_xor_sync(0xffffffffu, a, 1));
            a  = fmaxf(a,  __shfl_xor_sync(0xffffffffu, a, 2));
            c2 = fmaxf(c2, __shfl_xor_sync(0xffffffffu, c2, 1));
            c2 = fmaxf(c2, __shfl_xor_sync(0xffffffffu, c2, 2));
            mnew[mt][0] = fmaxf(m8[mt][0], a);
            mnew[mt][1] = fmaxf(m8[mt][1], c2);
            float fa0 = fex2(m8[mt][0] - mnew[mt][0]);
            float fa1 = fex2(m8[mt][1] - mnew[mt][1]);
            m8[mt][0] = mnew[mt][0]; m8[mt][1] = mnew[mt][1];
            l8[mt][0] *= fa0; l8[mt][1] *= fa1;
            #pragma unroll
            for (int nt = 0; nt < 8; nt++) {
                O[mt][nt][0] *= fa0; O[mt][nt][1] *= fa0;
                O[mt][nt][2] *= fa1; O[mt][nt][3] *= fa1;
            }
        }

        // ---- p = F' * 2^(s - m), kept in registers; accumulate partial l ----
        #pragma unroll
        for (int mt = 0; mt < 2; mt++) {
            int rl = wm + (mt << 4) + frow;
            #pragma unroll
            for (int nt = 0; nt < 8; nt++) {
                const __half* fp = Fg + (long long)rl * N_ + j0 + wn * 64 + (nt << 3) + (fcol << 1);
                float2 f0 = __half22float2(*(const __half2*)fp);
                float2 f1 = __half22float2(*(const __half2*)(fp + 8 * N_));
                float p0 = f0.x * fex2(S[mt][nt][0] - mnew[mt][0]);
                float p1 = f0.y * fex2(S[mt][nt][1] - mnew[mt][0]);
                float p2 = f1.x * fex2(S[mt][nt][2] - mnew[mt][1]);
                float p3 = f1.y * fex2(S[mt][nt][3] - mnew[mt][1]);
                l8[mt][0] += p0 + p1;
                l8[mt][1] += p2 + p3;
                S[mt][nt][0] = p0; S[mt][nt][1] = p1;
                S[mt][nt][2] = p2; S[mt][nt][3] = p3;
            }
        }

        // ---- O += P @ V  (A-operand packed from S registers; warp's j-half) ----
        #pragma unroll
        for (int ks = 0; ks < 4; ks++) {
            uint32_t ah[2][4], al[2][4];
            #pragma unroll
            for (int mt = 0; mt < 2; mt++) {
                ah[mt][0] = pack_bf(S[mt][2*ks][0],   S[mt][2*ks][1]);
                ah[mt][1] = pack_bf(S[mt][2*ks][2],   S[mt][2*ks][3]);
                ah[mt][2] = pack_bf(S[mt][2*ks+1][0], S[mt][2*ks+1][1]);
                ah[mt][3] = pack_bf(S[mt][2*ks+1][2], S[mt][2*ks+1][3]);
                al[mt][0] = resid_bf(S[mt][2*ks][0],   S[mt][2*ks][1],   ah[mt][0]);
                al[mt][1] = resid_bf(S[mt][2*ks][2],   S[mt][2*ks][3],   ah[mt][1]);
                al[mt][2] = resid_bf(S[mt][2*ks+1][0], S[mt][2*ks+1][1], ah[mt][2]);
                al[mt][3] = resid_bf(S[mt][2*ks+1][2], S[mt][2*ks+1][3], ah[mt][3]);
            }
            int r0v = (wn * 32 + ks * 8 + fcol) * VSP;
            int r1v = (wn * 32 + ks * 8 + fcol + 4) * VSP;
            #pragma unroll
            for (int nt = 0; nt < 8; nt++) {
                int nb = (nt << 3) + frow;
                uint2 v0 = *(const uint2*)&fsm[FVP + 2 * (r0v + nb)];
                uint2 v1 = *(const uint2*)&fsm[FVP + 2 * (r1v + nb)];
                uint32_t bh[2] = {v0.x, v1.x};
                uint32_t bl[2] = {v0.y, v1.y};
                #pragma unroll
                for (int mt = 0; mt < 2; mt++) {
                    mma_bf16(O[mt][nt], ah[mt], bh);
                    mma_bf16(O[mt][nt], al[mt], bh);
                    mma_bf16(O[mt][nt], ah[mt], bl);
                }
            }
        }
    }

    // ---- final reduction: quad-reduce l; merge halves (split-softmax) ----
    #pragma unroll
    for (int mt = 0; mt < 2; mt++) {
        l8[mt][0] += __shfl_xor_sync(0xffffffffu, l8[mt][0], 1);
        l8[mt][0] += __shfl_xor_sync(0xffffffffu, l8[mt][0], 2);
        l8[mt][1] += __shfl_xor_sync(0xffffffffu, l8[mt][1], 1);
        l8[mt][1] += __shfl_xor_sync(0xffffffffu, l8[mt][1], 2);
    }
    __syncthreads();   // all S/PV reads done before OX reuse
    if (wn == 1) {
        #pragma unroll
        for (int mt = 0; mt < 2; mt++) {
            int rl = wm + (mt << 4) + frow;
            #pragma unroll
            for (int nt = 0; nt < 8; nt++) {
                int col = (nt << 3) + (fcol << 1);
                *(float2*)&OX[rl * 64 + col]       = make_float2(O[mt][nt][0], O[mt][nt][1]);
                *(float2*)&OX[(rl + 8) * 64 + col] = make_float2(O[mt][nt][2], O[mt][nt][3]);
            }
            if (fcol == 0) {
                LX[rl] = l8[mt][0];
                LX[rl + 8] = l8[mt][1];
                MX[rl] = m8[mt][0];
                MX[rl + 8] = m8[mt][1];
            }
        }
    }
    __syncthreads();
    if (wn == 0) {
        #pragma unroll
        for (int mt = 0; mt < 2; mt++) {
            int rl = wm + (mt << 4) + frow;
            float mo0 = MX[rl], mo1 = MX[rl + 8];
            float M0 = fmaxf(m8[mt][0], mo0);
            float M1 = fmaxf(m8[mt][1], mo1);
            float s00 = fex2(m8[mt][0] - M0), s01 = fex2(mo0 - M0);
            float s10 = fex2(m8[mt][1] - M1), s11 = fex2(mo1 - M1);
            float inv0 = 1.0f / (l8[mt][0] * s00 + LX[rl] * s01);
            float inv1 = 1.0f / (l8[mt][1] * s10 + LX[rl + 8] * s11);
            #pragma unroll
            for (int nt = 0; nt < 8; nt++) {
                int col = (nt << 3) + (fcol << 1);
                float2 x0 = *(const float2*)&OX[rl * 64 + col];
                float2 x1 = *(const float2*)&OX[(rl + 8) * 64 + col];
                float2 u0 = make_float2((O[mt][nt][0] * s00 + x0.x * s01) * inv0,
                                        (O[mt][nt][1] * s00 + x0.y * s01) * inv0);
                float2 u1 = make_float2((O[mt][nt][2] * s10 + x1.x * s11) * inv1,
                                        (O[mt][nt][3] * s10 + x1.y * s11) * inv1);
                *(float2*)(AOg + (long long)(i0 + rl) * D_ + col) = u0;
                *(float2*)(AOg + (long long)(i0 + rl + 8) * D_ + col) = u1;
            }
        }
    }
}

// ---------------- launch ----------------------------------------------------
extern "C" void kernel_launch(void* const* d_in, const int* in_sizes, int n_in,
                              void* d_out, int out_size) {
    const float* inq = (const float*)d_in[0];
    const float* ink = (const float*)d_in[1];
    const float* inv = (const float*)d_in[2];
    const float* box = (const float*)d_in[3];
    const int*   msk = (const int*)d_in[4];
    const void*  nob = d_in[5];
    const float* Wq = (const float*)d_in[6];  const float* bq = (const float*)d_in[7];
    const float* Wk = (const float*)d_in[8];  const float* bk = (const float*)d_in[9];
    const float* Wv = (const float*)d_in[10]; const float* bv = (const float*)d_in[11];
    const float* Wo = (const float*)d_in[12]; const float* bo = (const float*)d_in[13];
    const float* WG = (const float*)d_in[14]; const float* bG = (const float*)d_in[15];
    float* out = (float*)d_out;

    float *pq, *pk, *pv, *pao;
    cudaGetSymbolAddress((void**)&pq,  g_q);
    cudaGetSymbolAddress((void**)&pk,  g_k);
    cudaGetSymbolAddress((void**)&pv,  g_v);
    cudaGetSymbolAddress((void**)&pao, g_ao);

    cudaFuncSetAttribute(flash_kernel, cudaFuncAttributeMaxDynamicSharedMemorySize, FLASH_SMEM);
    cudaFuncSetAttribute(fused_qkv_geom, cudaFuncAttributeMaxDynamicSharedMemorySize, FUSED_SMEM);

    box_pre<<<32, 128>>>(box, nob);

    fused_qkv_geom<<<PROJ_BLOCKS + 2048, 256, FUSED_SMEM>>>(
        inq, ink, inv, Wq, Wk, Wv, bq, bk, bv, pq, pk, pv, WG, bG, msk);

    flash_kernel<<<dim3(4, H_, B_), 256, FLASH_SMEM>>>();

    dim3 gO(8, 32, 1);
    proj_gemm_single<<<gO, 256, PROJ_WORDS * 4>>>(pao, Wo, bo, out);
}